// round 11
// baseline (speedup 1.0000x reference)
#include <cuda_runtime.h>
#include <cuda_bf16.h>
#include <cstdint>

#define NT 256

// ---------------- global scratch (no runtime allocation allowed) ----------------
static __device__ float          g_seg[(size_t)50176 * 128];   // scatter-sum
static __device__ float          g_h0s[(size_t)50176 * 128];   // nodeF @ eW0(sender)
static __device__ float          g_h0r[(size_t)50176 * 128];   // nodeF @ eW0(receiver)
static __device__ float          g_h0n[(size_t)50176 * 128];   // nodeF @ nW0(node part)
static __device__ uint32_t       g_hph[(size_t)400128 * 64];   // hidden act hi-pairs (bf16x2)
static __device__ uint32_t       g_hpl[(size_t)400128 * 64];   // hidden act lo-pairs (bf16x2)
static __device__ __nv_bfloat16  g_wh[9 * 16384];              // weight hi, fragment-major
static __device__ __nv_bfloat16  g_wl[9 * 16384];              // weight lo, fragment-major

// ---------------- helpers ----------------
__device__ __forceinline__ void split2(float2 v, uint32_t& h, uint32_t& l) {
    __nv_bfloat162 hb = __floats2bfloat162_rn(v.x, v.y);
    float r0 = v.x - __bfloat162float(hb.x);
    float r1 = v.y - __bfloat162float(hb.y);
    __nv_bfloat162 lb = __floats2bfloat162_rn(r0, r1);
    h = *reinterpret_cast<const uint32_t*>(&hb);
    l = *reinterpret_cast<const uint32_t*>(&lb);
}
__device__ __forceinline__ void split2f(float x, float y, uint32_t& h, uint32_t& l) {
    split2(make_float2(x, y), h, l);
}
// m16n8k16 bf16 MMA, fp32 accumulate (baseline PTX, valid on sm_103).
__device__ __forceinline__ void mma4(float* c, const uint32_t* a, uint2 b) {
    asm("mma.sync.aligned.m16n8k16.row.col.f32.bf16.bf16.f32 "
        "{%0,%1,%2,%3}, {%4,%5,%6,%7}, {%8,%9}, {%0,%1,%2,%3};"
        : "+f"(c[0]), "+f"(c[1]), "+f"(c[2]), "+f"(c[3])
        : "r"(a[0]), "r"(a[1]), "r"(a[2]), "r"(a[3]), "r"(b.x), "r"(b.y));
}
// One K=16 step: wh loaded once, reused. 2 LDS.64 per 3 MMAs.
__device__ __forceinline__ void mma_step(float* acc, const uint32_t* ah,
                                         const uint32_t* al, const char* bbase) {
    #pragma unroll
    for (int t = 0; t < 16; ++t) {
        uint2 wh = *(const uint2*)(bbase + t * 256);
        uint2 wl = *(const uint2*)(bbase + 32768 + t * 256);
        mma4(&acc[t * 4], ah, wh);
        mma4(&acc[t * 4], ah, wl);
        mma4(&acc[t * 4], al, wh);
    }
}

// ---------------- prep kernels ----------------
__global__ void zero_seg_kernel(int n4) {
    int i = blockIdx.x * blockDim.x + threadIdx.x;
    if (i < n4) reinterpret_cast<float4*>(g_seg)[i] = make_float4(0.f, 0.f, 0.f, 0.f);
}
// All six weight matrices -> fragment-major bf16 hi/lo images, one launch.
// images: 0..2=eW0 chunks, 3=eW1, 4=eW2, 5..6=nW0 chunks, 7=nW1, 8=nW2
__global__ void prep_all_kernel(const float* __restrict__ eW0, const float* __restrict__ eW1,
                                const float* __restrict__ eW2, const float* __restrict__ nW0,
                                const float* __restrict__ nW1, const float* __restrict__ nW2) {
    int t = blockIdx.x * blockDim.x + threadIdx.x;
    if (t >= 1152 * 128) return;
    int kg = t >> 7, n = t & 127;
    const float* W; int k, baseImg;
    if      (kg < 384)  { W = eW0; k = kg;        baseImg = 0; }
    else if (kg < 512)  { W = eW1; k = kg - 384;  baseImg = 3; }
    else if (kg < 640)  { W = eW2; k = kg - 512;  baseImg = 4; }
    else if (kg < 896)  { W = nW0; k = kg - 640;  baseImg = 5; }
    else if (kg < 1024) { W = nW1; k = kg - 896;  baseImg = 7; }
    else                { W = nW2; k = kg - 1024; baseImg = 8; }
    float x = W[k * 128 + n];
    __nv_bfloat16 h = __float2bfloat16(x);
    __nv_bfloat16 l = __float2bfloat16(x - __bfloat162float(h));
    int chunk = k >> 7, kc = k & 127;
    int kstep = kc >> 4, kk = kc & 15;
    int reg = kk >> 3, kb = kk & 7;
    int lane = (n & 7) * 4 + (kb >> 1), cb = kb & 1;
    int frag = kstep * 16 + (n >> 3);
    size_t di = (size_t)(baseImg + chunk) * 16384 + (size_t)frag * 128 + lane * 4 + reg * 2 + cb;
    g_wh[di] = h;
    g_wl[di] = l;
}

// ---------------- SMEM ----------------
__device__ __forceinline__ void load_image(char* smem, int img, int tid) {
    const uint4* sh = (const uint4*)(g_wh + (size_t)img * 16384);
    const uint4* sl = (const uint4*)(g_wl + (size_t)img * 16384);
    uint4* dh = (uint4*)smem;
    uint4* dl = (uint4*)(smem + 32768);
    #pragma unroll
    for (int i = tid; i < 2048; i += NT) { dh[i] = sh[i]; dl[i] = sl[i]; }
}
#define SM_BIAS 65536
#define SM_G    66048
#define SM_BE   66560
#define SMEM_LAYER 67072
#define SMEM_PRE   65536

// ---------------- precompute: H0s/H0r/H0n = nodeF @ {eW0s, eW0r, nW0a} ----------------
__global__ __launch_bounds__(NT, 2)
void precomp_kernel(const float* __restrict__ nodef, int Nn, int ntiles,
                    int i0, int i1, int i2)
{
    extern __shared__ char smem[];
    const int tid = threadIdx.x, wid = tid >> 5, lane = tid & 31, q = lane & 3;
    const int rl = wid * 16 + (lane >> 2);
    const int imgs[3] = {i0, i1, i2};
    float* const outs[3] = {g_h0s, g_h0r, g_h0n};

    for (int j = 0; j < 3; ++j) {
        __syncthreads();
        load_image(smem, imgs[j], tid);
        __syncthreads();
        for (int tile = blockIdx.x; tile < ntiles; tile += gridDim.x) {
            const int gel = tile * 128 + rl, geh = gel + 8;
            const int gl = min(gel, Nn - 1), gh = min(geh, Nn - 1);
            const float* pl = nodef + (size_t)gl * 128;
            const float* ph = nodef + (size_t)gh * 128;
            float acc[64];
            #pragma unroll
            for (int i = 0; i < 64; ++i) acc[i] = 0.f;
            #pragma unroll
            for (int s = 0; s < 8; ++s) {
                const int k0 = s * 16 + q * 2;
                uint32_t ahf[4], alf[4];
                split2(*(const float2*)(pl + k0),     ahf[0], alf[0]);
                split2(*(const float2*)(ph + k0),     ahf[1], alf[1]);
                split2(*(const float2*)(pl + k0 + 8), ahf[2], alf[2]);
                split2(*(const float2*)(ph + k0 + 8), ahf[3], alf[3]);
                mma_step(acc, ahf, alf, smem + (s * 16) * 256 + (lane << 3));
            }
            float* o = outs[j];
            #pragma unroll
            for (int t = 0; t < 16; ++t) {
                const int col = t * 8 + q * 2;
                if (gel < Nn)
                    *(float2*)(o + (size_t)gel * 128 + col) = make_float2(acc[t * 4 + 0], acc[t * 4 + 1]);
                if (geh < Nn)
                    *(float2*)(o + (size_t)geh * 128 + col) = make_float2(acc[t * 4 + 2], acc[t * 4 + 3]);
            }
        }
    }
}

// ---------------- per-layer persistent kernel ----------------
// MODE: 0=edge-L0, 1=mid (E1/N1), 2=edge-L2 (LN+resid+scatter),
//       3=node-L0, 4=node-L2 (LN+resid)
template<int MODE>
__global__ __launch_bounds__(NT, 2)
void layer_k(const float* __restrict__ src,     // MODE 0: edgef
             const int* __restrict__ senders,
             const int* __restrict__ receivers,
             const float* __restrict__ bias,
             const float* __restrict__ gma, const float* __restrict__ bta,
             const float* __restrict__ resid,
             float* __restrict__ out,
             int M, int ntiles, int img)
{
    extern __shared__ char smem[];
    const int tid = threadIdx.x, wid = tid >> 5, lane = tid & 31, q = lane & 3;
    const int rl = wid * 16 + (lane >> 2);

    load_image(smem, img, tid);
    for (int i = tid; i < 128; i += NT) {
        ((float*)(smem + SM_BIAS))[i] = bias[i];
        if (MODE == 2 || MODE == 4) {
            ((float*)(smem + SM_G ))[i] = gma[i];
            ((float*)(smem + SM_BE))[i] = bta[i];
        }
    }
    __syncthreads();

    for (int tile = blockIdx.x; tile < ntiles; tile += gridDim.x) {
        const int gel = tile * 128 + rl, geh = gel + 8;
        const int gl = min(gel, M - 1), gh = min(geh, M - 1);

        float acc[64];

        // ---- accumulator init ----
        if (MODE == 0) {
            const float* asl = g_h0s + (size_t)senders[gl]   * 128;
            const float* ash = g_h0s + (size_t)senders[gh]   * 128;
            const float* arl = g_h0r + (size_t)receivers[gl] * 128;
            const float* arh = g_h0r + (size_t)receivers[gh] * 128;
            #pragma unroll
            for (int t = 0; t < 16; ++t) {
                const int col = t * 8 + q * 2;
                float2 a = *(const float2*)(asl + col);
                float2 b = *(const float2*)(arl + col);
                float2 c = *(const float2*)(ash + col);
                float2 d = *(const float2*)(arh + col);
                acc[t * 4 + 0] = a.x + b.x; acc[t * 4 + 1] = a.y + b.y;
                acc[t * 4 + 2] = c.x + d.x; acc[t * 4 + 3] = c.y + d.y;
            }
        } else if (MODE == 3) {
            const float* al_ = g_h0n + (size_t)gl * 128;
            const float* ah_ = g_h0n + (size_t)gh * 128;
            #pragma unroll
            for (int t = 0; t < 16; ++t) {
                const int col = t * 8 + q * 2;
                float2 a = *(const float2*)(al_ + col);
                float2 c = *(const float2*)(ah_ + col);
                acc[t * 4 + 0] = a.x; acc[t * 4 + 1] = a.y;
                acc[t * 4 + 2] = c.x; acc[t * 4 + 3] = c.y;
            }
        } else {
            #pragma unroll
            for (int j = 0; j < 64; ++j) acc[j] = 0.f;
        }

        // ---- K=128 MMA ----
        if (MODE == 0 || MODE == 3) {
            const float* base = (MODE == 0) ? src : g_seg;
            const float* pl = base + (size_t)gl * 128;
            const float* ph = base + (size_t)gh * 128;
            #pragma unroll
            for (int s = 0; s < 8; ++s) {
                const int k0 = s * 16 + q * 2;
                uint32_t ahf[4], alf[4];
                split2(*(const float2*)(pl + k0),     ahf[0], alf[0]);
                split2(*(const float2*)(ph + k0),     ahf[1], alf[1]);
                split2(*(const float2*)(pl + k0 + 8), ahf[2], alf[2]);
                split2(*(const float2*)(ph + k0 + 8), ahf[3], alf[3]);
                mma_step(acc, ahf, alf, smem + (s * 16) * 256 + (lane << 3));
            }
        } else {
            const uint32_t* hl_ = g_hph + (size_t)gl * 64;
            const uint32_t* hh_ = g_hph + (size_t)gh * 64;
            const uint32_t* ll_ = g_hpl + (size_t)gl * 64;
            const uint32_t* lh_ = g_hpl + (size_t)gh * 64;
            #pragma unroll
            for (int s = 0; s < 8; ++s) {
                const int p0 = s * 8 + q, p1 = p0 + 4;
                uint32_t ahf[4], alf[4];
                ahf[0] = hl_[p0]; ahf[1] = hh_[p0];
                ahf[2] = hl_[p1]; ahf[3] = hh_[p1];
                alf[0] = ll_[p0]; alf[1] = lh_[p0];
                alf[2] = ll_[p1]; alf[3] = lh_[p1];
                mma_step(acc, ahf, alf, smem + (s * 16) * 256 + (lane << 3));
            }
        }

        // ---- epilogue ----
        if (MODE == 0 || MODE == 1 || MODE == 3) {
            const float* b = (const float*)(smem + SM_BIAS);
            uint32_t* oph_l = g_hph + (size_t)gel * 64;
            uint32_t* oph_h = g_hph + (size_t)geh * 64;
            uint32_t* opl_l = g_hpl + (size_t)gel * 64;
            uint32_t* opl_h = g_hpl + (size_t)geh * 64;
            #pragma unroll
            for (int t = 0; t < 16; ++t) {
                float2 bz = *(const float2*)(b + t * 8 + q * 2);
                float v0 = fmaxf(acc[t * 4 + 0] + bz.x, 0.f);
                float v1 = fmaxf(acc[t * 4 + 1] + bz.y, 0.f);
                float v2 = fmaxf(acc[t * 4 + 2] + bz.x, 0.f);
                float v3 = fmaxf(acc[t * 4 + 3] + bz.y, 0.f);
                uint32_t h0, l0, h1, l1;
                split2f(v0, v1, h0, l0);
                split2f(v2, v3, h1, l1);
                const int p = t * 4 + q;
                if (gel < M) { oph_l[p] = h0; opl_l[p] = l0; }
                if (geh < M) { oph_h[p] = h1; opl_h[p] = l1; }
            }
        } else {
            const float* b = (const float*)(smem + SM_BIAS);
            float sl = 0.f, ssl = 0.f, sh2 = 0.f, ssh = 0.f;
            #pragma unroll
            for (int t = 0; t < 16; ++t) {
                float2 bz = *(const float2*)(b + t * 8 + q * 2);
                float v0 = acc[t * 4 + 0] + bz.x, v1 = acc[t * 4 + 1] + bz.y;
                float v2 = acc[t * 4 + 2] + bz.x, v3 = acc[t * 4 + 3] + bz.y;
                acc[t * 4 + 0] = v0; acc[t * 4 + 1] = v1;
                acc[t * 4 + 2] = v2; acc[t * 4 + 3] = v3;
                sl  += v0 + v1; ssl = fmaf(v0, v0, fmaf(v1, v1, ssl));
                sh2 += v2 + v3; ssh = fmaf(v2, v2, fmaf(v3, v3, ssh));
            }
            #pragma unroll
            for (int o = 1; o <= 2; o <<= 1) {
                sl  += __shfl_xor_sync(0xffffffffu, sl,  o);
                ssl += __shfl_xor_sync(0xffffffffu, ssl, o);
                sh2 += __shfl_xor_sync(0xffffffffu, sh2, o);
                ssh += __shfl_xor_sync(0xffffffffu, ssh, o);
            }
            const float mul = sl  * (1.f / 128.f);
            const float muh = sh2 * (1.f / 128.f);
            const float rsl = rsqrtf(ssl * (1.f / 128.f) - mul * mul + 1e-5f);
            const float rsh = rsqrtf(ssh * (1.f / 128.f) - muh * muh + 1e-5f);

            int rvl = 0, rvh = 0;
            if (MODE == 2) { rvl = receivers[gl]; rvh = receivers[gh]; }
            const float* gw = (const float*)(smem + SM_G);
            const float* bw = (const float*)(smem + SM_BE);

            #pragma unroll
            for (int t = 0; t < 16; ++t) {
                const int col = t * 8 + q * 2;
                float2 gg = *(const float2*)(gw + col);
                float2 bb = *(const float2*)(bw + col);
                if (gel < M) {
                    float ne0 = fmaf(gg.x, (acc[t * 4 + 0] - mul) * rsl, bb.x);
                    float ne1 = fmaf(gg.y, (acc[t * 4 + 1] - mul) * rsl, bb.y);
                    float2 rf = *(const float2*)(resid + (size_t)gel * 128 + col);
                    *(float2*)(out + (size_t)gel * 128 + col) = make_float2(ne0 + rf.x, ne1 + rf.y);
                    if (MODE == 2) {
                        atomicAdd(&g_seg[(size_t)rvl * 128 + col + 0], ne0);
                        atomicAdd(&g_seg[(size_t)rvl * 128 + col + 1], ne1);
                    }
                }
                if (geh < M) {
                    float ne2 = fmaf(gg.x, (acc[t * 4 + 2] - muh) * rsh, bb.x);
                    float ne3 = fmaf(gg.y, (acc[t * 4 + 3] - muh) * rsh, bb.y);
                    float2 rf = *(const float2*)(resid + (size_t)geh * 128 + col);
                    *(float2*)(out + (size_t)geh * 128 + col) = make_float2(ne2 + rf.x, ne3 + rf.y);
                    if (MODE == 2) {
                        atomicAdd(&g_seg[(size_t)rvh * 128 + col + 0], ne2);
                        atomicAdd(&g_seg[(size_t)rvh * 128 + col + 1], ne3);
                    }
                }
            }
        }
    }
}

// ---------------- launch ----------------
extern "C" void kernel_launch(void* const* d_in, const int* in_sizes, int n_in,
                              void* d_out, int out_size)
{
    const float* nodef     = (const float*)d_in[0];
    const float* edgef     = (const float*)d_in[1];
    const int*   senders   = (const int*)d_in[2];
    const int*   receivers = (const int*)d_in[3];
    const float* eW0 = (const float*)d_in[4];  const float* eb0 = (const float*)d_in[5];
    const float* eW1 = (const float*)d_in[6];  const float* eb1 = (const float*)d_in[7];
    const float* eW2 = (const float*)d_in[8];  const float* eb2 = (const float*)d_in[9];
    const float* eg  = (const float*)d_in[10]; const float* ebt = (const float*)d_in[11];
    const float* nW0 = (const float*)d_in[12]; const float* nb0 = (const float*)d_in[13];
    const float* nW1 = (const float*)d_in[14]; const float* nb1 = (const float*)d_in[15];
    const float* nW2 = (const float*)d_in[16]; const float* nb2 = (const float*)d_in[17];
    const float* ng  = (const float*)d_in[18]; const float* nbt = (const float*)d_in[19];

    const int N = in_sizes[0] / 128;
    const int E = in_sizes[2];
    float* out_node = (float*)d_out;
    float* out_edge = out_node + (size_t)N * 128;

    cudaFuncSetAttribute(precomp_kernel,
                         cudaFuncAttributeMaxDynamicSharedMemorySize, SMEM_PRE);
    cudaFuncSetAttribute(layer_k<0>, cudaFuncAttributeMaxDynamicSharedMemorySize, SMEM_LAYER);
    cudaFuncSetAttribute(layer_k<1>, cudaFuncAttributeMaxDynamicSharedMemorySize, SMEM_LAYER);
    cudaFuncSetAttribute(layer_k<2>, cudaFuncAttributeMaxDynamicSharedMemorySize, SMEM_LAYER);
    cudaFuncSetAttribute(layer_k<3>, cudaFuncAttributeMaxDynamicSharedMemorySize, SMEM_LAYER);
    cudaFuncSetAttribute(layer_k<4>, cudaFuncAttributeMaxDynamicSharedMemorySize, SMEM_LAYER);

    prep_all_kernel<<<(1152 * 128 + 255) / 256, 256>>>(eW0, eW1, eW2, nW0, nW1, nW2);
    zero_seg_kernel<<<(N * 32 + 255) / 256, 256>>>(N * 32);

    const int ntile_n = (N + 127) / 128;
    const int ntile_e = (E + 127) / 128;
    const int G = 296;

    // H0s / H0r / H0n over nodes
    precomp_kernel<<<G, NT, SMEM_PRE>>>(nodef, N, ntile_n, 0, 1, 5);

    // edge MLP: L0 -> L1 -> L2(+LN,resid,scatter)
    layer_k<0><<<G, NT, SMEM_LAYER>>>(edgef, senders, receivers, eb0,
                                      nullptr, nullptr, nullptr, nullptr, E, ntile_e, 2);
    layer_k<1><<<G, NT, SMEM_LAYER>>>(nullptr, nullptr, nullptr, eb1,
                                      nullptr, nullptr, nullptr, nullptr, E, ntile_e, 3);
    layer_k<2><<<G, NT, SMEM_LAYER>>>(nullptr, nullptr, receivers, eb2,
                                      eg, ebt, edgef, out_edge, E, ntile_e, 4);

    // node MLP: L0 -> L1 -> L2(+LN,resid)
    layer_k<3><<<G, NT, SMEM_LAYER>>>(nullptr, nullptr, nullptr, nb0,
                                      nullptr, nullptr, nullptr, nullptr, N, ntile_n, 6);
    layer_k<1><<<G, NT, SMEM_LAYER>>>(nullptr, nullptr, nullptr, nb1,
                                      nullptr, nullptr, nullptr, nullptr, N, ntile_n, 7);
    layer_k<4><<<G, NT, SMEM_LAYER>>>(nullptr, nullptr, nullptr, nb2,
                                      ng, nbt, nodef, out_node, N, ntile_n, 8);
}

// round 12
// speedup vs baseline: 3.0499x; 3.0499x over previous
#include <cuda_runtime.h>
#include <cuda_bf16.h>
#include <cstdint>

#define NT 256

// ---------------- global scratch (no runtime allocation allowed) ----------------
static __device__ float          g_seg[(size_t)50176 * 128];   // scatter-sum
static __device__ float          g_h0s[(size_t)50176 * 128];   // nodeF @ eW0(sender)
static __device__ float          g_h0r[(size_t)50176 * 128];   // nodeF @ eW0(receiver)
static __device__ float          g_h0n[(size_t)50176 * 128];   // nodeF @ nW0(node part)
static __device__ __nv_bfloat16  g_wh[9 * 16384];              // weight hi, fragment-major
static __device__ __nv_bfloat16  g_wl[9 * 16384];              // weight lo, fragment-major

// ---------------- helpers ----------------
__device__ __forceinline__ void split2(float2 v, uint32_t& h, uint32_t& l) {
    __nv_bfloat162 hb = __floats2bfloat162_rn(v.x, v.y);
    float r0 = v.x - __bfloat162float(hb.x);
    float r1 = v.y - __bfloat162float(hb.y);
    __nv_bfloat162 lb = __floats2bfloat162_rn(r0, r1);
    h = *reinterpret_cast<const uint32_t*>(&hb);
    l = *reinterpret_cast<const uint32_t*>(&lb);
}
__device__ __forceinline__ void split2f(float x, float y, uint32_t& h, uint32_t& l) {
    split2(make_float2(x, y), h, l);
}
// m16n8k16 bf16 MMA, fp32 accumulate (baseline PTX, valid on sm_103).
__device__ __forceinline__ void mma4(float* c, const uint32_t* a, uint2 b) {
    asm("mma.sync.aligned.m16n8k16.row.col.f32.bf16.bf16.f32 "
        "{%0,%1,%2,%3}, {%4,%5,%6,%7}, {%8,%9}, {%0,%1,%2,%3};"
        : "+f"(c[0]), "+f"(c[1]), "+f"(c[2]), "+f"(c[3])
        : "r"(a[0]), "r"(a[1]), "r"(a[2]), "r"(a[3]), "r"(b.x), "r"(b.y));
}
// One K=16 step: wh loaded once, reused. 2 LDS.64 per 3 MMAs.
__device__ __forceinline__ void mma_step(float* acc, const uint32_t* ah,
                                         const uint32_t* al, const char* bbase) {
    #pragma unroll
    for (int t = 0; t < 16; ++t) {
        uint2 wh = *(const uint2*)(bbase + t * 256);
        uint2 wl = *(const uint2*)(bbase + 32768 + t * 256);
        mma4(&acc[t * 4], ah, wh);
        mma4(&acc[t * 4], ah, wl);
        mma4(&acc[t * 4], al, wh);
    }
}

// ---------------- prep kernels ----------------
__global__ void zero_seg_kernel(int n4) {
    int i = blockIdx.x * blockDim.x + threadIdx.x;
    if (i < n4) reinterpret_cast<float4*>(g_seg)[i] = make_float4(0.f, 0.f, 0.f, 0.f);
}
// All six weight matrices -> fragment-major bf16 hi/lo images, one launch.
// images: 0..2=eW0 chunks, 3=eW1, 4=eW2, 5..6=nW0 chunks, 7=nW1, 8=nW2
__global__ void prep_all_kernel(const float* __restrict__ eW0, const float* __restrict__ eW1,
                                const float* __restrict__ eW2, const float* __restrict__ nW0,
                                const float* __restrict__ nW1, const float* __restrict__ nW2) {
    int t = blockIdx.x * blockDim.x + threadIdx.x;
    if (t >= 1152 * 128) return;
    int kg = t >> 7, n = t & 127;
    const float* W; int k, baseImg;
    if      (kg < 384)  { W = eW0; k = kg;        baseImg = 0; }
    else if (kg < 512)  { W = eW1; k = kg - 384;  baseImg = 3; }
    else if (kg < 640)  { W = eW2; k = kg - 512;  baseImg = 4; }
    else if (kg < 896)  { W = nW0; k = kg - 640;  baseImg = 5; }
    else if (kg < 1024) { W = nW1; k = kg - 896;  baseImg = 7; }
    else                { W = nW2; k = kg - 1024; baseImg = 8; }
    float x = W[k * 128 + n];
    __nv_bfloat16 h = __float2bfloat16(x);
    __nv_bfloat16 l = __float2bfloat16(x - __bfloat162float(h));
    int chunk = k >> 7, kc = k & 127;
    int kstep = kc >> 4, kk = kc & 15;
    int reg = kk >> 3, kb = kk & 7;
    int lane = (n & 7) * 4 + (kb >> 1), cb = kb & 1;
    int frag = kstep * 16 + (n >> 3);
    size_t di = (size_t)(baseImg + chunk) * 16384 + (size_t)frag * 128 + lane * 4 + reg * 2 + cb;
    g_wh[di] = h;
    g_wl[di] = l;
}

// ---------------- SMEM map (bytes) — single cycling B buffer ----------------
#define SM_BH   0        // weight image hi fragments (32768)
#define SM_BL   32768    // weight image lo fragments (32768)
#define SM_ALO  65536    // per-warp A-lo fragments  (8 warps x 4096)
#define SM_B0   98304
#define SM_B1   98816
#define SM_B2   99328
#define SM_G    99840
#define SM_BE   100352
#define SMEM_TOTAL 100864
#define SMEM_PRE   65536

// Modest unroll: keeps copy temps small so nothing live spills around the copy.
__device__ __forceinline__ void load_image(char* smem, int img, int tid) {
    const uint4* sh = (const uint4*)(g_wh + (size_t)img * 16384);
    const uint4* sl = (const uint4*)(g_wl + (size_t)img * 16384);
    uint4* dh = (uint4*)(smem + SM_BH);
    uint4* dl = (uint4*)(smem + SM_BL);
    #pragma unroll 2
    for (int i = tid; i < 2048; i += NT) { dh[i] = sh[i]; dl[i] = sl[i]; }
}

// ---------------- precompute: H0s/H0r/H0n = nodeF @ {eW0s, eW0r, nW0a} ----------------
__global__ __launch_bounds__(NT, 2)
void precomp_kernel(const float* __restrict__ nodef, int Nn, int ntiles,
                    int i0, int i1, int i2)
{
    extern __shared__ char smem[];
    const int tid = threadIdx.x, wid = tid >> 5, lane = tid & 31, q = lane & 3;
    const int rl = wid * 16 + (lane >> 2);
    const int imgs[3] = {i0, i1, i2};
    float* const outs[3] = {g_h0s, g_h0r, g_h0n};

    for (int j = 0; j < 3; ++j) {
        __syncthreads();
        load_image(smem, imgs[j], tid);
        __syncthreads();
        for (int tile = blockIdx.x; tile < ntiles; tile += gridDim.x) {
            const int gel = tile * 128 + rl, geh = gel + 8;
            const int gl = min(gel, Nn - 1), gh = min(geh, Nn - 1);
            const float* pl = nodef + (size_t)gl * 128;
            const float* ph = nodef + (size_t)gh * 128;
            float acc[64];
            #pragma unroll
            for (int i = 0; i < 64; ++i) acc[i] = 0.f;
            #pragma unroll
            for (int s = 0; s < 8; ++s) {
                const int k0 = s * 16 + q * 2;
                uint32_t ahf[4], alf[4];
                split2(*(const float2*)(pl + k0),     ahf[0], alf[0]);
                split2(*(const float2*)(ph + k0),     ahf[1], alf[1]);
                split2(*(const float2*)(pl + k0 + 8), ahf[2], alf[2]);
                split2(*(const float2*)(ph + k0 + 8), ahf[3], alf[3]);
                mma_step(acc, ahf, alf, smem + (s * 16) * 256 + (lane << 3));
            }
            float* o = outs[j];
            #pragma unroll
            for (int t = 0; t < 16; ++t) {
                const int col = t * 8 + q * 2;
                if (gel < Nn)
                    *(float2*)(o + (size_t)gel * 128 + col) = make_float2(acc[t * 4 + 0], acc[t * 4 + 1]);
                if (geh < Nn)
                    *(float2*)(o + (size_t)geh * 128 + col) = make_float2(acc[t * 4 + 2], acc[t * 4 + 3]);
            }
        }
    }
}

// ---------------- fused 3-layer MLP + LN + residual (+scatter) ----------------
// One block = one 128-row tile; 2 blocks/SM; B buffer cycles W0part->W1->W2.
// CRITICAL ordering: weight image is loaded BEFORE acc is materialized, so the
// 64 accumulator registers are never live across a copy loop or barrier.
template<bool IS_EDGE>
__global__ __launch_bounds__(NT, 2)
void gnn3(const float* __restrict__ chunkA_in,   // edge: edgef; node: (g_seg used)
          const int*   __restrict__ senders,
          const int*   __restrict__ receivers,
          const float* __restrict__ b0, const float* __restrict__ b1,
          const float* __restrict__ b2,
          const float* __restrict__ gma, const float* __restrict__ bta,
          const float* __restrict__ resid,
          float* __restrict__ out, int M, int wimg0)
{
    extern __shared__ char smem[];
    const int tid = threadIdx.x, wid = tid >> 5, lane = tid & 31, q = lane & 3;
    const int rl = wid * 16 + (lane >> 2);
    const int r0 = blockIdx.x * 128;

    // stage biases / LN params + FIRST weight image, then one barrier.
    for (int i = tid; i < 128; i += NT) {
        ((float*)(smem + SM_B0))[i] = b0[i];
        ((float*)(smem + SM_B1))[i] = b1[i];
        ((float*)(smem + SM_B2))[i] = b2[i];
        ((float*)(smem + SM_G ))[i] = gma[i];
        ((float*)(smem + SM_BE))[i] = bta[i];
    }
    load_image(smem, wimg0, tid);
    __syncthreads();

    const int gel = r0 + rl, geh = gel + 8;
    const int gl = min(gel, M - 1), gh = min(geh, M - 1);

    float acc[64];

    // ---- acc init from precomputed layer-0 partials (AFTER image is resident) ----
    if (IS_EDGE) {
        const float* asl = g_h0s + (size_t)senders[gl]   * 128;
        const float* ash = g_h0s + (size_t)senders[gh]   * 128;
        const float* arl = g_h0r + (size_t)receivers[gl] * 128;
        const float* arh = g_h0r + (size_t)receivers[gh] * 128;
        #pragma unroll
        for (int t = 0; t < 16; ++t) {
            const int col = t * 8 + q * 2;
            float2 a = *(const float2*)(asl + col);
            float2 b = *(const float2*)(arl + col);
            float2 c = *(const float2*)(ash + col);
            float2 d = *(const float2*)(arh + col);
            acc[t * 4 + 0] = a.x + b.x; acc[t * 4 + 1] = a.y + b.y;
            acc[t * 4 + 2] = c.x + d.x; acc[t * 4 + 3] = c.y + d.y;
        }
    } else {
        const float* al_ = g_h0n + (size_t)gl * 128;
        const float* ah_ = g_h0n + (size_t)gh * 128;
        #pragma unroll
        for (int t = 0; t < 16; ++t) {
            const int col = t * 8 + q * 2;
            float2 a = *(const float2*)(al_ + col);
            float2 c = *(const float2*)(ah_ + col);
            acc[t * 4 + 0] = a.x; acc[t * 4 + 1] = a.y;
            acc[t * 4 + 2] = c.x; acc[t * 4 + 3] = c.y;
        }
    }

    // ---- layer 0: one K=128 chunk (edgef / seg-sum) ----
    {
        const float* chunkA = IS_EDGE ? chunkA_in : g_seg;
        const float* pl = chunkA + (size_t)gl * 128;
        const float* ph = chunkA + (size_t)gh * 128;
        #pragma unroll
        for (int s = 0; s < 8; ++s) {
            const int k0 = s * 16 + q * 2;
            uint32_t ahf[4], alf[4];
            split2(*(const float2*)(pl + k0),     ahf[0], alf[0]);
            split2(*(const float2*)(ph + k0),     ahf[1], alf[1]);
            split2(*(const float2*)(pl + k0 + 8), ahf[2], alf[2]);
            split2(*(const float2*)(ph + k0 + 8), ahf[3], alf[3]);
            mma_step(acc, ahf, alf, smem + (s * 16) * 256 + (lane << 3));
        }
    }

    // ---- layers 1, 2 ----
    uint32_t Ahi[32];
    uint32_t* aloW = (uint32_t*)(smem + SM_ALO + wid * 4096);
    #pragma unroll
    for (int L = 1; L <= 2; ++L) {
        // transition: bias + ReLU + split. After this, acc is DEAD (re-zeroed below),
        // so only Ahi[32] is live across the image copy.
        const float* bias = (const float*)(smem + (L == 1 ? SM_B0 : SM_B1));
        #pragma unroll
        for (int s = 0; s < 8; ++s) {
            const int t0 = 2 * s, t1 = 2 * s + 1;
            float2 bz0 = *(const float2*)(bias + t0 * 8 + q * 2);
            float2 bz1 = *(const float2*)(bias + t1 * 8 + q * 2);
            float v00 = fmaxf(acc[t0 * 4 + 0] + bz0.x, 0.f);
            float v01 = fmaxf(acc[t0 * 4 + 1] + bz0.y, 0.f);
            float v02 = fmaxf(acc[t0 * 4 + 2] + bz0.x, 0.f);
            float v03 = fmaxf(acc[t0 * 4 + 3] + bz0.y, 0.f);
            float v10 = fmaxf(acc[t1 * 4 + 0] + bz1.x, 0.f);
            float v11 = fmaxf(acc[t1 * 4 + 1] + bz1.y, 0.f);
            float v12 = fmaxf(acc[t1 * 4 + 2] + bz1.x, 0.f);
            float v13 = fmaxf(acc[t1 * 4 + 3] + bz1.y, 0.f);
            uint32_t l0, l1, l2, l3;
            split2f(v00, v01, Ahi[s * 4 + 0], l0);
            split2f(v02, v03, Ahi[s * 4 + 1], l1);
            split2f(v10, v11, Ahi[s * 4 + 2], l2);
            split2f(v12, v13, Ahi[s * 4 + 3], l3);
            aloW[(s * 4 + 0) * 32 + lane] = l0;
            aloW[(s * 4 + 1) * 32 + lane] = l1;
            aloW[(s * 4 + 2) * 32 + lane] = l2;
            aloW[(s * 4 + 3) * 32 + lane] = l3;
        }
        __syncthreads();                // all warps done reading previous image
        load_image(smem, wimg0 + L, tid);
        __syncthreads();
        #pragma unroll
        for (int j = 0; j < 64; ++j) acc[j] = 0.f;
        #pragma unroll
        for (int s = 0; s < 8; ++s) {
            uint32_t alf[4];
            #pragma unroll
            for (int j = 0; j < 4; ++j) alf[j] = aloW[(s * 4 + j) * 32 + lane];
            mma_step(acc, &Ahi[s * 4], alf, smem + (s * 16) * 256 + (lane << 3));
        }
    }

    // ---- final: bias + LayerNorm + residual (+ scatter) ----
    {
        const float* bias = (const float*)(smem + SM_B2);
        float sl = 0.f, ssl = 0.f, sh2 = 0.f, ssh = 0.f;
        #pragma unroll
        for (int t = 0; t < 16; ++t) {
            float2 bz = *(const float2*)(bias + t * 8 + q * 2);
            float v0 = acc[t * 4 + 0] + bz.x, v1 = acc[t * 4 + 1] + bz.y;
            float v2 = acc[t * 4 + 2] + bz.x, v3 = acc[t * 4 + 3] + bz.y;
            acc[t * 4 + 0] = v0; acc[t * 4 + 1] = v1;
            acc[t * 4 + 2] = v2; acc[t * 4 + 3] = v3;
            sl  += v0 + v1; ssl = fmaf(v0, v0, fmaf(v1, v1, ssl));
            sh2 += v2 + v3; ssh = fmaf(v2, v2, fmaf(v3, v3, ssh));
        }
        #pragma unroll
        for (int o = 1; o <= 2; o <<= 1) {
            sl  += __shfl_xor_sync(0xffffffffu, sl,  o);
            ssl += __shfl_xor_sync(0xffffffffu, ssl, o);
            sh2 += __shfl_xor_sync(0xffffffffu, sh2, o);
            ssh += __shfl_xor_sync(0xffffffffu, ssh, o);
        }
        const float mul = sl  * (1.f / 128.f);
        const float muh = sh2 * (1.f / 128.f);
        const float rsl = rsqrtf(ssl * (1.f / 128.f) - mul * mul + 1e-5f);
        const float rsh = rsqrtf(ssh * (1.f / 128.f) - muh * muh + 1e-5f);

        int rvl = 0, rvh = 0;
        if (IS_EDGE) { rvl = receivers[gl]; rvh = receivers[gh]; }
        const float* gw = (const float*)(smem + SM_G);
        const float* bw = (const float*)(smem + SM_BE);

        #pragma unroll
        for (int t = 0; t < 16; ++t) {
            const int col = t * 8 + q * 2;
            float2 gg = *(const float2*)(gw + col);
            float2 bb = *(const float2*)(bw + col);
            if (gel < M) {
                float ne0 = fmaf(gg.x, (acc[t * 4 + 0] - mul) * rsl, bb.x);
                float ne1 = fmaf(gg.y, (acc[t * 4 + 1] - mul) * rsl, bb.y);
                float2 rf = *(const float2*)(resid + (size_t)gel * 128 + col);
                *(float2*)(out + (size_t)gel * 128 + col) = make_float2(ne0 + rf.x, ne1 + rf.y);
                if (IS_EDGE) {
                    atomicAdd(&g_seg[(size_t)rvl * 128 + col + 0], ne0);
                    atomicAdd(&g_seg[(size_t)rvl * 128 + col + 1], ne1);
                }
            }
            if (geh < M) {
                float ne2 = fmaf(gg.x, (acc[t * 4 + 2] - muh) * rsh, bb.x);
                float ne3 = fmaf(gg.y, (acc[t * 4 + 3] - muh) * rsh, bb.y);
                float2 rf = *(const float2*)(resid + (size_t)geh * 128 + col);
                *(float2*)(out + (size_t)geh * 128 + col) = make_float2(ne2 + rf.x, ne3 + rf.y);
                if (IS_EDGE) {
                    atomicAdd(&g_seg[(size_t)rvh * 128 + col + 0], ne2);
                    atomicAdd(&g_seg[(size_t)rvh * 128 + col + 1], ne3);
                }
            }
        }
    }
}

// ---------------- launch ----------------
extern "C" void kernel_launch(void* const* d_in, const int* in_sizes, int n_in,
                              void* d_out, int out_size)
{
    const float* nodef     = (const float*)d_in[0];
    const float* edgef     = (const float*)d_in[1];
    const int*   senders   = (const int*)d_in[2];
    const int*   receivers = (const int*)d_in[3];
    const float* eW0 = (const float*)d_in[4];  const float* eb0 = (const float*)d_in[5];
    const float* eW1 = (const float*)d_in[6];  const float* eb1 = (const float*)d_in[7];
    const float* eW2 = (const float*)d_in[8];  const float* eb2 = (const float*)d_in[9];
    const float* eg  = (const float*)d_in[10]; const float* ebt = (const float*)d_in[11];
    const float* nW0 = (const float*)d_in[12]; const float* nb0 = (const float*)d_in[13];
    const float* nW1 = (const float*)d_in[14]; const float* nb1 = (const float*)d_in[15];
    const float* nW2 = (const float*)d_in[16]; const float* nb2 = (const float*)d_in[17];
    const float* ng  = (const float*)d_in[18]; const float* nbt = (const float*)d_in[19];

    const int N = in_sizes[0] / 128;
    const int E = in_sizes[2];
    float* out_node = (float*)d_out;
    float* out_edge = out_node + (size_t)N * 128;

    cudaFuncSetAttribute(precomp_kernel,
                         cudaFuncAttributeMaxDynamicSharedMemorySize, SMEM_PRE);
    cudaFuncSetAttribute(gnn3<true>,
                         cudaFuncAttributeMaxDynamicSharedMemorySize, SMEM_TOTAL);
    cudaFuncSetAttribute(gnn3<false>,
                         cudaFuncAttributeMaxDynamicSharedMemorySize, SMEM_TOTAL);

    // weight images: 0=eW0s 1=eW0r 2=eW0e 3=eW1 4=eW2 5=nW0a 6=nW0b 7=nW1 8=nW2
    prep_all_kernel<<<(1152 * 128 + 255) / 256, 256>>>(eW0, eW1, eW2, nW0, nW1, nW2);
    zero_seg_kernel<<<(N * 32 + 255) / 256, 256>>>(N * 32);

    const int ntile_n = (N + 127) / 128;

    // H0s / H0r / H0n precompute over nodes (image-outer, 2 blocks/SM)
    precomp_kernel<<<296, NT, SMEM_PRE>>>(nodef, N, ntile_n, 0, 1, 5);

    // edge pass
    gnn3<true><<<(E + 127) / 128, NT, SMEM_TOTAL>>>(
        edgef, senders, receivers,
        eb0, eb1, eb2, eg, ebt, edgef, out_edge, E, 2);

    // node pass
    gnn3<false><<<ntile_n, NT, SMEM_TOTAL>>>(
        nullptr, nullptr, nullptr,
        nb0, nb1, nb2, ng, nbt, nodef, out_node, N, 6);
}

// round 13
// speedup vs baseline: 3.8563x; 1.2644x over previous
#include <cuda_runtime.h>
#include <cuda_fp16.h>
#include <cstdint>

#define NT 256

// ---------------- global scratch (no runtime allocation allowed) ----------------
static __device__ float   g_seg[(size_t)50176 * 128];   // scatter-sum
static __device__ float   g_h0s[(size_t)50176 * 128];   // nodeF @ eW0(sender)
static __device__ float   g_h0r[(size_t)50176 * 128];   // nodeF @ eW0(receiver)
static __device__ float   g_h0n[(size_t)50176 * 128];   // nodeF @ nW0(node part)
static __device__ __half  g_wh[9 * 16384];              // weight hi (fp16), fragment-major

// ---------------- helpers ----------------
// fp16 split: x = h + l, h = fp16(x) (rel 2^-11), l = fp16(x - h)
__device__ __forceinline__ void split2(float2 v, uint32_t& h, uint32_t& l) {
    __half2 hb = __floats2half2_rn(v.x, v.y);
    float r0 = v.x - __half2float(__low2half(hb));
    float r1 = v.y - __half2float(__high2half(hb));
    __half2 lb = __floats2half2_rn(r0, r1);
    h = *reinterpret_cast<const uint32_t*>(&hb);
    l = *reinterpret_cast<const uint32_t*>(&lb);
}
__device__ __forceinline__ void split2f(float x, float y, uint32_t& h, uint32_t& l) {
    split2(make_float2(x, y), h, l);
}
// m16n8k16 fp16 MMA, fp32 accumulate (baseline PTX, valid on sm_103).
__device__ __forceinline__ void mma4(float* c, const uint32_t* a, uint2 b) {
    asm("mma.sync.aligned.m16n8k16.row.col.f32.f16.f16.f32 "
        "{%0,%1,%2,%3}, {%4,%5,%6,%7}, {%8,%9}, {%0,%1,%2,%3};"
        : "+f"(c[0]), "+f"(c[1]), "+f"(c[2]), "+f"(c[3])
        : "r"(a[0]), "r"(a[1]), "r"(a[2]), "r"(a[3]), "r"(b.x), "r"(b.y));
}
// One K=16 step: wh loaded ONCE per (t), shared by both A terms. 1 LDS.64 / 2 MMAs.
__device__ __forceinline__ void mma_step(float* acc, const uint32_t* ah,
                                         const uint32_t* al, const char* bbase) {
    #pragma unroll
    for (int t = 0; t < 16; ++t) {
        uint2 wh = *(const uint2*)(bbase + t * 256);
        mma4(&acc[t * 4], ah, wh);
        mma4(&acc[t * 4], al, wh);
    }
}

// ---------------- async copy of one 32KB weight image ----------------
__device__ __forceinline__ void cp_img(void* smem_dst, int img, int tid) {
    uint32_t d = (uint32_t)__cvta_generic_to_shared(smem_dst);
    const uint4* src = (const uint4*)(g_wh + (size_t)img * 16384);
    #pragma unroll
    for (int i = tid; i < 2048; i += NT)
        asm volatile("cp.async.ca.shared.global [%0], [%1], 16;"
                     :: "r"(d + i * 16), "l"(src + i));
    asm volatile("cp.async.commit_group;" ::: "memory");
}
__device__ __forceinline__ void cp_wait_all() {
    asm volatile("cp.async.wait_group 0;" ::: "memory");
}

// ---------------- prep kernels ----------------
__global__ void zero_seg_kernel(int n4) {
    int i = blockIdx.x * blockDim.x + threadIdx.x;
    if (i < n4) reinterpret_cast<float4*>(g_seg)[i] = make_float4(0.f, 0.f, 0.f, 0.f);
}
// All six weight matrices -> fragment-major fp16 images, one launch.
// images: 0..2=eW0 chunks, 3=eW1, 4=eW2, 5..6=nW0 chunks, 7=nW1, 8=nW2
__global__ void prep_all_kernel(const float* __restrict__ eW0, const float* __restrict__ eW1,
                                const float* __restrict__ eW2, const float* __restrict__ nW0,
                                const float* __restrict__ nW1, const float* __restrict__ nW2) {
    int t = blockIdx.x * blockDim.x + threadIdx.x;
    if (t >= 1152 * 128) return;
    int kg = t >> 7, n = t & 127;
    const float* W; int k, baseImg;
    if      (kg < 384)  { W = eW0; k = kg;        baseImg = 0; }
    else if (kg < 512)  { W = eW1; k = kg - 384;  baseImg = 3; }
    else if (kg < 640)  { W = eW2; k = kg - 512;  baseImg = 4; }
    else if (kg < 896)  { W = nW0; k = kg - 640;  baseImg = 5; }
    else if (kg < 1024) { W = nW1; k = kg - 896;  baseImg = 7; }
    else                { W = nW2; k = kg - 1024; baseImg = 8; }
    float x = W[k * 128 + n];
    int chunk = k >> 7, kc = k & 127;
    int kstep = kc >> 4, kk = kc & 15;
    int reg = kk >> 3, kb = kk & 7;
    int lane = (n & 7) * 4 + (kb >> 1), cb = kb & 1;
    int frag = kstep * 16 + (n >> 3);
    size_t di = (size_t)(baseImg + chunk) * 16384 + (size_t)frag * 128 + lane * 4 + reg * 2 + cb;
    g_wh[di] = __float2half_rn(x);
}

// ---------------- SMEM maps (bytes) ----------------
#define SM_BUF0 0        // weight image buffer 0 (32768)
#define SM_BUF1 32768    // weight image buffer 1 (32768)
#define SM_ALO  65536    // per-warp A-lo fragments (8 warps x 4096)
#define SM_B0   98304
#define SM_B1   98816
#define SM_B2   99328
#define SM_G    99840
#define SM_BE   100352
#define SMEM_TOTAL 100864
#define SMEM_PRE   32768

// ---------------- precompute: H0s/H0r/H0n = nodeF @ {eW0s, eW0r, nW0a} ----------------
__global__ __launch_bounds__(NT, 2)
void precomp_kernel(const float* __restrict__ nodef, int Nn, int ntiles,
                    int i0, int i1, int i2)
{
    extern __shared__ char smem[];
    const int tid = threadIdx.x, wid = tid >> 5, lane = tid & 31, q = lane & 3;
    const int rl = wid * 16 + (lane >> 2);
    const int imgs[3] = {i0, i1, i2};
    float* const outs[3] = {g_h0s, g_h0r, g_h0n};

    for (int j = 0; j < 3; ++j) {
        __syncthreads();
        cp_img(smem, imgs[j], tid);
        cp_wait_all();
        __syncthreads();
        for (int tile = blockIdx.x; tile < ntiles; tile += gridDim.x) {
            const int gel = tile * 128 + rl, geh = gel + 8;
            const int gl = min(gel, Nn - 1), gh = min(geh, Nn - 1);
            const float* pl = nodef + (size_t)gl * 128;
            const float* ph = nodef + (size_t)gh * 128;
            float acc[64];
            #pragma unroll
            for (int i = 0; i < 64; ++i) acc[i] = 0.f;
            #pragma unroll
            for (int s = 0; s < 8; ++s) {
                const int k0 = s * 16 + q * 2;
                uint32_t ahf[4], alf[4];
                split2(*(const float2*)(pl + k0),     ahf[0], alf[0]);
                split2(*(const float2*)(ph + k0),     ahf[1], alf[1]);
                split2(*(const float2*)(pl + k0 + 8), ahf[2], alf[2]);
                split2(*(const float2*)(ph + k0 + 8), ahf[3], alf[3]);
                mma_step(acc, ahf, alf, smem + (s * 16) * 256 + (lane << 3));
            }
            float* o = outs[j];
            #pragma unroll
            for (int t = 0; t < 16; ++t) {
                const int col = t * 8 + q * 2;
                if (gel < Nn)
                    *(float2*)(o + (size_t)gel * 128 + col) = make_float2(acc[t * 4 + 0], acc[t * 4 + 1]);
                if (geh < Nn)
                    *(float2*)(o + (size_t)geh * 128 + col) = make_float2(acc[t * 4 + 2], acc[t * 4 + 3]);
            }
        }
    }
}

// ---------------- fused 3-layer MLP + LN + residual (+scatter) ----------------
// One block = one 128-row tile; 2 blocks/SM. Weight images double-buffered via
// cp.async so each layer's copy overlaps the previous layer's MMA.
template<bool IS_EDGE>
__global__ __launch_bounds__(NT, 2)
void gnn3(const float* __restrict__ chunkA_in,   // edge: edgef; node: (g_seg used)
          const int*   __restrict__ senders,
          const int*   __restrict__ receivers,
          const float* __restrict__ b0, const float* __restrict__ b1,
          const float* __restrict__ b2,
          const float* __restrict__ gma, const float* __restrict__ bta,
          const float* __restrict__ resid,
          float* __restrict__ out, int M, int wimg0)
{
    extern __shared__ char smem[];
    const int tid = threadIdx.x, wid = tid >> 5, lane = tid & 31, q = lane & 3;
    const int rl = wid * 16 + (lane >> 2);
    const int r0 = blockIdx.x * 128;

    // prologue: start img0 copy async, then stage params (overlap)
    cp_img(smem + SM_BUF0, wimg0, tid);
    for (int i = tid; i < 128; i += NT) {
        ((float*)(smem + SM_B0))[i] = b0[i];
        ((float*)(smem + SM_B1))[i] = b1[i];
        ((float*)(smem + SM_B2))[i] = b2[i];
        ((float*)(smem + SM_G ))[i] = gma[i];
        ((float*)(smem + SM_BE))[i] = bta[i];
    }

    const int gel = r0 + rl, geh = gel + 8;
    const int gl = min(gel, M - 1), gh = min(geh, M - 1);

    float acc[64];

    // ---- acc init from precomputed layer-0 partials (overlaps img0 copy) ----
    if (IS_EDGE) {
        const float* asl = g_h0s + (size_t)senders[gl]   * 128;
        const float* ash = g_h0s + (size_t)senders[gh]   * 128;
        const float* arl = g_h0r + (size_t)receivers[gl] * 128;
        const float* arh = g_h0r + (size_t)receivers[gh] * 128;
        #pragma unroll
        for (int t = 0; t < 16; ++t) {
            const int col = t * 8 + q * 2;
            float2 a = *(const float2*)(asl + col);
            float2 b = *(const float2*)(arl + col);
            float2 c = *(const float2*)(ash + col);
            float2 d = *(const float2*)(arh + col);
            acc[t * 4 + 0] = a.x + b.x; acc[t * 4 + 1] = a.y + b.y;
            acc[t * 4 + 2] = c.x + d.x; acc[t * 4 + 3] = c.y + d.y;
        }
    } else {
        const float* al_ = g_h0n + (size_t)gl * 128;
        const float* ah_ = g_h0n + (size_t)gh * 128;
        #pragma unroll
        for (int t = 0; t < 16; ++t) {
            const int col = t * 8 + q * 2;
            float2 a = *(const float2*)(al_ + col);
            float2 c = *(const float2*)(ah_ + col);
            acc[t * 4 + 0] = a.x; acc[t * 4 + 1] = a.y;
            acc[t * 4 + 2] = c.x; acc[t * 4 + 3] = c.y;
        }
    }

    cp_wait_all();
    __syncthreads();                    // buf0 ready for everyone
    cp_img(smem + SM_BUF1, wimg0 + 1, tid);   // prefetch L1 image during L0 MMA

    // ---- layer 0: one K=128 chunk (edgef / seg-sum), B in buf0 ----
    {
        const float* chunkA = IS_EDGE ? chunkA_in : g_seg;
        const float* pl = chunkA + (size_t)gl * 128;
        const float* ph = chunkA + (size_t)gh * 128;
        #pragma unroll
        for (int s = 0; s < 8; ++s) {
            const int k0 = s * 16 + q * 2;
            uint32_t ahf[4], alf[4];
            split2(*(const float2*)(pl + k0),     ahf[0], alf[0]);
            split2(*(const float2*)(ph + k0),     ahf[1], alf[1]);
            split2(*(const float2*)(pl + k0 + 8), ahf[2], alf[2]);
            split2(*(const float2*)(ph + k0 + 8), ahf[3], alf[3]);
            mma_step(acc, ahf, alf, smem + SM_BUF0 + (s * 16) * 256 + (lane << 3));
        }
    }

    // ---- layers 1, 2 ----
    uint32_t Ahi[32];
    uint32_t* aloW = (uint32_t*)(smem + SM_ALO + wid * 4096);
    #pragma unroll
    for (int L = 1; L <= 2; ++L) {
        // transition: bias + ReLU + split; acc dead afterwards (re-zeroed).
        const float* bias = (const float*)(smem + (L == 1 ? SM_B0 : SM_B1));
        #pragma unroll
        for (int s = 0; s < 8; ++s) {
            const int t0 = 2 * s, t1 = 2 * s + 1;
            float2 bz0 = *(const float2*)(bias + t0 * 8 + q * 2);
            float2 bz1 = *(const float2*)(bias + t1 * 8 + q * 2);
            float v00 = fmaxf(acc[t0 * 4 + 0] + bz0.x, 0.f);
            float v01 = fmaxf(acc[t0 * 4 + 1] + bz0.y, 0.f);
            float v02 = fmaxf(acc[t0 * 4 + 2] + bz0.x, 0.f);
            float v03 = fmaxf(acc[t0 * 4 + 3] + bz0.y, 0.f);
            float v10 = fmaxf(acc[t1 * 4 + 0] + bz1.x, 0.f);
            float v11 = fmaxf(acc[t1 * 4 + 1] + bz1.y, 0.f);
            float v12 = fmaxf(acc[t1 * 4 + 2] + bz1.x, 0.f);
            float v13 = fmaxf(acc[t1 * 4 + 3] + bz1.y, 0.f);
            uint32_t l0, l1, l2, l3;
            split2f(v00, v01, Ahi[s * 4 + 0], l0);
            split2f(v02, v03, Ahi[s * 4 + 1], l1);
            split2f(v10, v11, Ahi[s * 4 + 2], l2);
            split2f(v12, v13, Ahi[s * 4 + 3], l3);
            aloW[(s * 4 + 0) * 32 + lane] = l0;
            aloW[(s * 4 + 1) * 32 + lane] = l1;
            aloW[(s * 4 + 2) * 32 + lane] = l2;
            aloW[(s * 4 + 3) * 32 + lane] = l3;
        }
        cp_wait_all();                 // this layer's image landed
        __syncthreads();               // and everyone is done with the old buffer
        if (L == 1)                    // prefetch L2 image into buf0 during L1 MMA
            cp_img(smem + SM_BUF0, wimg0 + 2, tid);
        #pragma unroll
        for (int j = 0; j < 64; ++j) acc[j] = 0.f;
        const char* bb = smem + (L == 1 ? SM_BUF1 : SM_BUF0);
        #pragma unroll
        for (int s = 0; s < 8; ++s) {
            uint32_t alf[4];
            #pragma unroll
            for (int j = 0; j < 4; ++j) alf[j] = aloW[(s * 4 + j) * 32 + lane];
            mma_step(acc, &Ahi[s * 4], alf, bb + (s * 16) * 256 + (lane << 3));
        }
    }

    // ---- final: bias + LayerNorm + residual (+ scatter) ----
    {
        const float* bias = (const float*)(smem + SM_B2);
        float sl = 0.f, ssl = 0.f, sh2 = 0.f, ssh = 0.f;
        #pragma unroll
        for (int t = 0; t < 16; ++t) {
            float2 bz = *(const float2*)(bias + t * 8 + q * 2);
            float v0 = acc[t * 4 + 0] + bz.x, v1 = acc[t * 4 + 1] + bz.y;
            float v2 = acc[t * 4 + 2] + bz.x, v3 = acc[t * 4 + 3] + bz.y;
            acc[t * 4 + 0] = v0; acc[t * 4 + 1] = v1;
            acc[t * 4 + 2] = v2; acc[t * 4 + 3] = v3;
            sl  += v0 + v1; ssl = fmaf(v0, v0, fmaf(v1, v1, ssl));
            sh2 += v2 + v3; ssh = fmaf(v2, v2, fmaf(v3, v3, ssh));
        }
        #pragma unroll
        for (int o = 1; o <= 2; o <<= 1) {
            sl  += __shfl_xor_sync(0xffffffffu, sl,  o);
            ssl += __shfl_xor_sync(0xffffffffu, ssl, o);
            sh2 += __shfl_xor_sync(0xffffffffu, sh2, o);
            ssh += __shfl_xor_sync(0xffffffffu, ssh, o);
        }
        const float mul = sl  * (1.f / 128.f);
        const float muh = sh2 * (1.f / 128.f);
        const float rsl = rsqrtf(ssl * (1.f / 128.f) - mul * mul + 1e-5f);
        const float rsh = rsqrtf(ssh * (1.f / 128.f) - muh * muh + 1e-5f);

        int rvl = 0, rvh = 0;
        if (IS_EDGE) { rvl = receivers[gl]; rvh = receivers[gh]; }
        const float* gw = (const float*)(smem + SM_G);
        const float* bw = (const float*)(smem + SM_BE);

        #pragma unroll
        for (int t = 0; t < 16; ++t) {
            const int col = t * 8 + q * 2;
            float2 gg = *(const float2*)(gw + col);
            float2 bb = *(const float2*)(bw + col);
            if (gel < M) {
                float ne0 = fmaf(gg.x, (acc[t * 4 + 0] - mul) * rsl, bb.x);
                float ne1 = fmaf(gg.y, (acc[t * 4 + 1] - mul) * rsl, bb.y);
                float2 rf = *(const float2*)(resid + (size_t)gel * 128 + col);
                *(float2*)(out + (size_t)gel * 128 + col) = make_float2(ne0 + rf.x, ne1 + rf.y);
                if (IS_EDGE) {
                    atomicAdd(&g_seg[(size_t)rvl * 128 + col + 0], ne0);
                    atomicAdd(&g_seg[(size_t)rvl * 128 + col + 1], ne1);
                }
            }
            if (geh < M) {
                float ne2 = fmaf(gg.x, (acc[t * 4 + 2] - muh) * rsh, bb.x);
                float ne3 = fmaf(gg.y, (acc[t * 4 + 3] - muh) * rsh, bb.y);
                float2 rf = *(const float2*)(resid + (size_t)geh * 128 + col);
                *(float2*)(out + (size_t)geh * 128 + col) = make_float2(ne2 + rf.x, ne3 + rf.y);
                if (IS_EDGE) {
                    atomicAdd(&g_seg[(size_t)rvh * 128 + col + 0], ne2);
                    atomicAdd(&g_seg[(size_t)rvh * 128 + col + 1], ne3);
                }
            }
        }
    }
}

// ---------------- launch ----------------
extern "C" void kernel_launch(void* const* d_in, const int* in_sizes, int n_in,
                              void* d_out, int out_size)
{
    const float* nodef     = (const float*)d_in[0];
    const float* edgef     = (const float*)d_in[1];
    const int*   senders   = (const int*)d_in[2];
    const int*   receivers = (const int*)d_in[3];
    const float* eW0 = (const float*)d_in[4];  const float* eb0 = (const float*)d_in[5];
    const float* eW1 = (const float*)d_in[6];  const float* eb1 = (const float*)d_in[7];
    const float* eW2 = (const float*)d_in[8];  const float* eb2 = (const float*)d_in[9];
    const float* eg  = (const float*)d_in[10]; const float* ebt = (const float*)d_in[11];
    const float* nW0 = (const float*)d_in[12]; const float* nb0 = (const float*)d_in[13];
    const float* nW1 = (const float*)d_in[14]; const float* nb1 = (const float*)d_in[15];
    const float* nW2 = (const float*)d_in[16]; const float* nb2 = (const float*)d_in[17];
    const float* ng  = (const float*)d_in[18]; const float* nbt = (const float*)d_in[19];

    const int N = in_sizes[0] / 128;
    const int E = in_sizes[2];
    float* out_node = (float*)d_out;
    float* out_edge = out_node + (size_t)N * 128;

    cudaFuncSetAttribute(precomp_kernel,
                         cudaFuncAttributeMaxDynamicSharedMemorySize, SMEM_PRE);
    cudaFuncSetAttribute(gnn3<true>,
                         cudaFuncAttributeMaxDynamicSharedMemorySize, SMEM_TOTAL);
    cudaFuncSetAttribute(gnn3<false>,
                         cudaFuncAttributeMaxDynamicSharedMemorySize, SMEM_TOTAL);

    // weight images: 0=eW0s 1=eW0r 2=eW0e 3=eW1 4=eW2 5=nW0a 6=nW0b 7=nW1 8=nW2
    prep_all_kernel<<<(1152 * 128 + 255) / 256, 256>>>(eW0, eW1, eW2, nW0, nW1, nW2);
    zero_seg_kernel<<<(N * 32 + 255) / 256, 256>>>(N * 32);

    const int ntile_n = (N + 127) / 128;

    // H0s / H0r / H0n precompute over nodes
    precomp_kernel<<<296, NT, SMEM_PRE>>>(nodef, N, ntile_n, 0, 1, 5);

    // edge pass
    gnn3<true><<<(E + 127) / 128, NT, SMEM_TOTAL>>>(
        edgef, senders, receivers,
        eb0, eb1, eb2, eg, ebt, edgef, out_edge, E, 2);

    // node pass
    gnn3<false><<<ntile_n, NT, SMEM_TOTAL>>>(
        nullptr, nullptr, nullptr,
        nb0, nb1, nb2, ng, nbt, nodef, out_node, N, 6);
}

// round 14
// speedup vs baseline: 5.3667x; 1.3917x over previous
#include <cuda_runtime.h>
#include <cuda_fp16.h>
#include <cstdint>

#define NT 256

// ---------------- global scratch (no runtime allocation allowed) ----------------
static __device__ float   g_seg[(size_t)50176 * 128];   // scatter-sum
static __device__ float   g_h0s[(size_t)50176 * 128];   // nodeF @ eW0(sender)
static __device__ float   g_h0r[(size_t)50176 * 128];   // nodeF @ eW0(receiver)
static __device__ float   g_h0n[(size_t)50176 * 128];   // nodeF @ nW0(node part)
static __device__ __half  g_wh[9 * 16384];              // weights (fp16), fragment-major

// ---------------- helpers ----------------
__device__ __forceinline__ uint32_t cvt2(float2 v) {
    __half2 h = __floats2half2_rn(v.x, v.y);
    return *reinterpret_cast<const uint32_t*>(&h);
}
__device__ __forceinline__ uint32_t cvt2f(float x, float y) {
    return cvt2(make_float2(x, y));
}
// m16n8k16 fp16 MMA, fp32 accumulate (baseline PTX, valid on sm_103).
__device__ __forceinline__ void mma4(float* c, const uint32_t* a, uint2 b) {
    asm("mma.sync.aligned.m16n8k16.row.col.f32.f16.f16.f32 "
        "{%0,%1,%2,%3}, {%4,%5,%6,%7}, {%8,%9}, {%0,%1,%2,%3};"
        : "+f"(c[0]), "+f"(c[1]), "+f"(c[2]), "+f"(c[3])
        : "r"(a[0]), "r"(a[1]), "r"(a[2]), "r"(a[3]), "r"(b.x), "r"(b.y));
}
// One K=16 step: 1 LDS.64 + 1 MMA per n-tile.
__device__ __forceinline__ void mma_step(float* acc, const uint32_t* ah, const char* bbase) {
    #pragma unroll
    for (int t = 0; t < 16; ++t) {
        uint2 wh = *(const uint2*)(bbase + t * 256);
        mma4(&acc[t * 4], ah, wh);
    }
}

// ---------------- async copy of one 32KB weight image ----------------
__device__ __forceinline__ void cp_img(void* smem_dst, int img, int tid) {
    uint32_t d = (uint32_t)__cvta_generic_to_shared(smem_dst);
    const uint4* src = (const uint4*)(g_wh + (size_t)img * 16384);
    #pragma unroll
    for (int i = tid; i < 2048; i += NT)
        asm volatile("cp.async.ca.shared.global [%0], [%1], 16;"
                     :: "r"(d + i * 16), "l"(src + i));
    asm volatile("cp.async.commit_group;" ::: "memory");
}
__device__ __forceinline__ void cp_wait_all() {
    asm volatile("cp.async.wait_group 0;" ::: "memory");
}

// ---------------- prep kernels ----------------
__global__ void zero_seg_kernel(int n4) {
    int i = blockIdx.x * blockDim.x + threadIdx.x;
    if (i < n4) reinterpret_cast<float4*>(g_seg)[i] = make_float4(0.f, 0.f, 0.f, 0.f);
}
// All six weight matrices -> fragment-major fp16 images, one launch.
// images: 0..2=eW0 chunks, 3=eW1, 4=eW2, 5..6=nW0 chunks, 7=nW1, 8=nW2
__global__ void prep_all_kernel(const float* __restrict__ eW0, const float* __restrict__ eW1,
                                const float* __restrict__ eW2, const float* __restrict__ nW0,
                                const float* __restrict__ nW1, const float* __restrict__ nW2) {
    int t = blockIdx.x * blockDim.x + threadIdx.x;
    if (t >= 1152 * 128) return;
    int kg = t >> 7, n = t & 127;
    const float* W; int k, baseImg;
    if      (kg < 384)  { W = eW0; k = kg;        baseImg = 0; }
    else if (kg < 512)  { W = eW1; k = kg - 384;  baseImg = 3; }
    else if (kg < 640)  { W = eW2; k = kg - 512;  baseImg = 4; }
    else if (kg < 896)  { W = nW0; k = kg - 640;  baseImg = 5; }
    else if (kg < 1024) { W = nW1; k = kg - 896;  baseImg = 7; }
    else                { W = nW2; k = kg - 1024; baseImg = 8; }
    float x = W[k * 128 + n];
    int chunk = k >> 7, kc = k & 127;
    int kstep = kc >> 4, kk = kc & 15;
    int reg = kk >> 3, kb = kk & 7;
    int lane = (n & 7) * 4 + (kb >> 1), cb = kb & 1;
    int frag = kstep * 16 + (n >> 3);
    size_t di = (size_t)(baseImg + chunk) * 16384 + (size_t)frag * 128 + lane * 4 + reg * 2 + cb;
    g_wh[di] = __float2half_rn(x);
}

// ---------------- SMEM maps (bytes) ----------------
#define SM_BUF0 0        // weight image buffer 0 (32768)
#define SM_BUF1 32768    // weight image buffer 1 (32768)
#define SM_B0   65536
#define SM_B1   66048
#define SM_B2   66560
#define SM_G    67072
#define SM_BE   67584
#define SMEM_TOTAL 68096
#define SMEM_PRE   32768

// ---------------- precompute: H0s/H0r/H0n = nodeF @ {eW0s, eW0r, nW0a} ----------------
__global__ __launch_bounds__(NT, 2)
void precomp_kernel(const float* __restrict__ nodef, int Nn, int ntiles,
                    int i0, int i1, int i2)
{
    extern __shared__ char smem[];
    const int tid = threadIdx.x, wid = tid >> 5, lane = tid & 31, q = lane & 3;
    const int rl = wid * 16 + (lane >> 2);
    const int imgs[3] = {i0, i1, i2};
    float* const outs[3] = {g_h0s, g_h0r, g_h0n};

    for (int j = 0; j < 3; ++j) {
        __syncthreads();
        cp_img(smem, imgs[j], tid);
        cp_wait_all();
        __syncthreads();
        for (int tile = blockIdx.x; tile < ntiles; tile += gridDim.x) {
            const int gel = tile * 128 + rl, geh = gel + 8;
            const int gl = min(gel, Nn - 1), gh = min(geh, Nn - 1);
            const float* pl = nodef + (size_t)gl * 128;
            const float* ph = nodef + (size_t)gh * 128;
            float acc[64];
            #pragma unroll
            for (int i = 0; i < 64; ++i) acc[i] = 0.f;
            #pragma unroll
            for (int s = 0; s < 8; ++s) {
                const int k0 = s * 16 + q * 2;
                uint32_t ahf[4];
                ahf[0] = cvt2(*(const float2*)(pl + k0));
                ahf[1] = cvt2(*(const float2*)(ph + k0));
                ahf[2] = cvt2(*(const float2*)(pl + k0 + 8));
                ahf[3] = cvt2(*(const float2*)(ph + k0 + 8));
                mma_step(acc, ahf, smem + (s * 16) * 256 + (lane << 3));
            }
            float* o = outs[j];
            #pragma unroll
            for (int t = 0; t < 16; ++t) {
                const int col = t * 8 + q * 2;
                if (gel < Nn)
                    *(float2*)(o + (size_t)gel * 128 + col) = make_float2(acc[t * 4 + 0], acc[t * 4 + 1]);
                if (geh < Nn)
                    *(float2*)(o + (size_t)geh * 128 + col) = make_float2(acc[t * 4 + 2], acc[t * 4 + 3]);
            }
        }
    }
}

// ---------------- fused 3-layer MLP + LN + residual (+scatter) ----------------
// One block = one 128-row tile; 2 blocks/SM. Weight images double-buffered via
// cp.async so each layer's copy overlaps the previous layer's MMA.
template<bool IS_EDGE>
__global__ __launch_bounds__(NT, 2)
void gnn3(const float* __restrict__ chunkA_in,   // edge: edgef; node: (g_seg used)
          const int*   __restrict__ senders,
          const int*   __restrict__ receivers,
          const float* __restrict__ b0, const float* __restrict__ b1,
          const float* __restrict__ b2,
          const float* __restrict__ gma, const float* __restrict__ bta,
          const float* __restrict__ resid,
          float* __restrict__ out, int M, int wimg0)
{
    extern __shared__ char smem[];
    const int tid = threadIdx.x, wid = tid >> 5, lane = tid & 31, q = lane & 3;
    const int rl = wid * 16 + (lane >> 2);
    const int r0 = blockIdx.x * 128;

    // prologue: start img0 copy async, then stage params (overlap)
    cp_img(smem + SM_BUF0, wimg0, tid);
    for (int i = tid; i < 128; i += NT) {
        ((float*)(smem + SM_B0))[i] = b0[i];
        ((float*)(smem + SM_B1))[i] = b1[i];
        ((float*)(smem + SM_B2))[i] = b2[i];
        ((float*)(smem + SM_G ))[i] = gma[i];
        ((float*)(smem + SM_BE))[i] = bta[i];
    }

    const int gel = r0 + rl, geh = gel + 8;
    const int gl = min(gel, M - 1), gh = min(geh, M - 1);

    float acc[64];

    // ---- acc init from precomputed layer-0 partials (overlaps img0 copy) ----
    if (IS_EDGE) {
        const float* asl = g_h0s + (size_t)senders[gl]   * 128;
        const float* ash = g_h0s + (size_t)senders[gh]   * 128;
        const float* arl = g_h0r + (size_t)receivers[gl] * 128;
        const float* arh = g_h0r + (size_t)receivers[gh] * 128;
        #pragma unroll
        for (int t = 0; t < 16; ++t) {
            const int col = t * 8 + q * 2;
            float2 a = *(const float2*)(asl + col);
            float2 b = *(const float2*)(arl + col);
            float2 c = *(const float2*)(ash + col);
            float2 d = *(const float2*)(arh + col);
            acc[t * 4 + 0] = a.x + b.x; acc[t * 4 + 1] = a.y + b.y;
            acc[t * 4 + 2] = c.x + d.x; acc[t * 4 + 3] = c.y + d.y;
        }
    } else {
        const float* al_ = g_h0n + (size_t)gl * 128;
        const float* ah_ = g_h0n + (size_t)gh * 128;
        #pragma unroll
        for (int t = 0; t < 16; ++t) {
            const int col = t * 8 + q * 2;
            float2 a = *(const float2*)(al_ + col);
            float2 c = *(const float2*)(ah_ + col);
            acc[t * 4 + 0] = a.x; acc[t * 4 + 1] = a.y;
            acc[t * 4 + 2] = c.x; acc[t * 4 + 3] = c.y;
        }
    }

    cp_wait_all();
    __syncthreads();                          // buf0 ready for everyone
    cp_img(smem + SM_BUF1, wimg0 + 1, tid);   // prefetch L1 image during L0 MMA

    // ---- layer 0: one K=128 chunk (edgef / seg-sum), B in buf0 ----
    {
        const float* chunkA = IS_EDGE ? chunkA_in : g_seg;
        const float* pl = chunkA + (size_t)gl * 128;
        const float* ph = chunkA + (size_t)gh * 128;
        #pragma unroll
        for (int s = 0; s < 8; ++s) {
            const int k0 = s * 16 + q * 2;
            uint32_t ahf[4];
            ahf[0] = cvt2(*(const float2*)(pl + k0));
            ahf[1] = cvt2(*(const float2*)(ph + k0));
            ahf[2] = cvt2(*(const float2*)(pl + k0 + 8));
            ahf[3] = cvt2(*(const float2*)(ph + k0 + 8));
            mma_step(acc, ahf, smem + SM_BUF0 + (s * 16) * 256 + (lane << 3));
        }
    }

    // ---- layers 1, 2 ----
    uint32_t Ahi[32];
    #pragma unroll
    for (int L = 1; L <= 2; ++L) {
        // transition: bias + ReLU + cvt; acc dead afterwards (re-zeroed).
        const float* bias = (const float*)(smem + (L == 1 ? SM_B0 : SM_B1));
        #pragma unroll
        for (int s = 0; s < 8; ++s) {
            const int t0 = 2 * s, t1 = 2 * s + 1;
            float2 bz0 = *(const float2*)(bias + t0 * 8 + q * 2);
            float2 bz1 = *(const float2*)(bias + t1 * 8 + q * 2);
            Ahi[s * 4 + 0] = cvt2f(fmaxf(acc[t0 * 4 + 0] + bz0.x, 0.f),
                                   fmaxf(acc[t0 * 4 + 1] + bz0.y, 0.f));
            Ahi[s * 4 + 1] = cvt2f(fmaxf(acc[t0 * 4 + 2] + bz0.x, 0.f),
                                   fmaxf(acc[t0 * 4 + 3] + bz0.y, 0.f));
            Ahi[s * 4 + 2] = cvt2f(fmaxf(acc[t1 * 4 + 0] + bz1.x, 0.f),
                                   fmaxf(acc[t1 * 4 + 1] + bz1.y, 0.f));
            Ahi[s * 4 + 3] = cvt2f(fmaxf(acc[t1 * 4 + 2] + bz1.x, 0.f),
                                   fmaxf(acc[t1 * 4 + 3] + bz1.y, 0.f));
        }
        cp_wait_all();                 // this layer's image landed
        __syncthreads();               // and everyone is done with the old buffer
        if (L == 1)                    // prefetch L2 image into buf0 during L1 MMA
            cp_img(smem + SM_BUF0, wimg0 + 2, tid);
        #pragma unroll
        for (int j = 0; j < 64; ++j) acc[j] = 0.f;
        const char* bb = smem + (L == 1 ? SM_BUF1 : SM_BUF0);
        #pragma unroll
        for (int s = 0; s < 8; ++s)
            mma_step(acc, &Ahi[s * 4], bb + (s * 16) * 256 + (lane << 3));
    }

    // ---- final: bias + LayerNorm + residual (+ scatter) ----
    {
        const float* bias = (const float*)(smem + SM_B2);
        float sl = 0.f, ssl = 0.f, sh2 = 0.f, ssh = 0.f;
        #pragma unroll
        for (int t = 0; t < 16; ++t) {
            float2 bz = *(const float2*)(bias + t * 8 + q * 2);
            float v0 = acc[t * 4 + 0] + bz.x, v1 = acc[t * 4 + 1] + bz.y;
            float v2 = acc[t * 4 + 2] + bz.x, v3 = acc[t * 4 + 3] + bz.y;
            acc[t * 4 + 0] = v0; acc[t * 4 + 1] = v1;
            acc[t * 4 + 2] = v2; acc[t * 4 + 3] = v3;
            sl  += v0 + v1; ssl = fmaf(v0, v0, fmaf(v1, v1, ssl));
            sh2 += v2 + v3; ssh = fmaf(v2, v2, fmaf(v3, v3, ssh));
        }
        #pragma unroll
        for (int o = 1; o <= 2; o <<= 1) {
            sl  += __shfl_xor_sync(0xffffffffu, sl,  o);
            ssl += __shfl_xor_sync(0xffffffffu, ssl, o);
            sh2 += __shfl_xor_sync(0xffffffffu, sh2, o);
            ssh += __shfl_xor_sync(0xffffffffu, ssh, o);
        }
        const float mul = sl  * (1.f / 128.f);
        const float muh = sh2 * (1.f / 128.f);
        const float rsl = rsqrtf(ssl * (1.f / 128.f) - mul * mul + 1e-5f);
        const float rsh = rsqrtf(ssh * (1.f / 128.f) - muh * muh + 1e-5f);

        int rvl = 0, rvh = 0;
        if (IS_EDGE) { rvl = receivers[gl]; rvh = receivers[gh]; }
        const float* gw = (const float*)(smem + SM_G);
        const float* bw = (const float*)(smem + SM_BE);

        #pragma unroll
        for (int t = 0; t < 16; ++t) {
            const int col = t * 8 + q * 2;
            float2 gg = *(const float2*)(gw + col);
            float2 bb = *(const float2*)(bw + col);
            if (gel < M) {
                float ne0 = fmaf(gg.x, (acc[t * 4 + 0] - mul) * rsl, bb.x);
                float ne1 = fmaf(gg.y, (acc[t * 4 + 1] - mul) * rsl, bb.y);
                float2 rf = *(const float2*)(resid + (size_t)gel * 128 + col);
                *(float2*)(out + (size_t)gel * 128 + col) = make_float2(ne0 + rf.x, ne1 + rf.y);
                if (IS_EDGE)
                    atomicAdd((float2*)&g_seg[(size_t)rvl * 128 + col], make_float2(ne0, ne1));
            }
            if (geh < M) {
                float ne2 = fmaf(gg.x, (acc[t * 4 + 2] - muh) * rsh, bb.x);
                float ne3 = fmaf(gg.y, (acc[t * 4 + 3] - muh) * rsh, bb.y);
                float2 rf = *(const float2*)(resid + (size_t)geh * 128 + col);
                *(float2*)(out + (size_t)geh * 128 + col) = make_float2(ne2 + rf.x, ne3 + rf.y);
                if (IS_EDGE)
                    atomicAdd((float2*)&g_seg[(size_t)rvh * 128 + col], make_float2(ne2, ne3));
            }
        }
    }
}

// ---------------- launch ----------------
extern "C" void kernel_launch(void* const* d_in, const int* in_sizes, int n_in,
                              void* d_out, int out_size)
{
    const float* nodef     = (const float*)d_in[0];
    const float* edgef     = (const float*)d_in[1];
    const int*   senders   = (const int*)d_in[2];
    const int*   receivers = (const int*)d_in[3];
    const float* eW0 = (const float*)d_in[4];  const float* eb0 = (const float*)d_in[5];
    const float* eW1 = (const float*)d_in[6];  const float* eb1 = (const float*)d_in[7];
    const float* eW2 = (const float*)d_in[8];  const float* eb2 = (const float*)d_in[9];
    const float* eg  = (const float*)d_in[10]; const float* ebt = (const float*)d_in[11];
    const float* nW0 = (const float*)d_in[12]; const float* nb0 = (const float*)d_in[13];
    const float* nW1 = (const float*)d_in[14]; const float* nb1 = (const float*)d_in[15];
    const float* nW2 = (const float*)d_in[16]; const float* nb2 = (const float*)d_in[17];
    const float* ng  = (const float*)d_in[18]; const float* nbt = (const float*)d_in[19];

    const int N = in_sizes[0] / 128;
    const int E = in_sizes[2];
    float* out_node = (float*)d_out;
    float* out_edge = out_node + (size_t)N * 128;

    cudaFuncSetAttribute(precomp_kernel,
                         cudaFuncAttributeMaxDynamicSharedMemorySize, SMEM_PRE);
    cudaFuncSetAttribute(gnn3<true>,
                         cudaFuncAttributeMaxDynamicSharedMemorySize, SMEM_TOTAL);
    cudaFuncSetAttribute(gnn3<false>,
                         cudaFuncAttributeMaxDynamicSharedMemorySize, SMEM_TOTAL);

    // weight images: 0=eW0s 1=eW0r 2=eW0e 3=eW1 4=eW2 5=nW0a 6=nW0b 7=nW1 8=nW2
    prep_all_kernel<<<(1152 * 128 + 255) / 256, 256>>>(eW0, eW1, eW2, nW0, nW1, nW2);
    zero_seg_kernel<<<(N * 32 + 255) / 256, 256>>>(N * 32);

    const int ntile_n = (N + 127) / 128;

    // H0s / H0r / H0n precompute over nodes
    precomp_kernel<<<296, NT, SMEM_PRE>>>(nodef, N, ntile_n, 0, 1, 5);

    // edge pass
    gnn3<true><<<(E + 127) / 128, NT, SMEM_TOTAL>>>(
        edgef, senders, receivers,
        eb0, eb1, eb2, eg, ebt, edgef, out_edge, E, 2);

    // node pass
    gnn3<false><<<ntile_n, NT, SMEM_TOTAL>>>(
        nullptr, nullptr, nullptr,
        nb0, nb1, nb2, ng, nbt, nodef, out_node, N, 6);
}